// round 1
// baseline (speedup 1.0000x reference)
#include <cuda_runtime.h>
#include <math.h>

#define Bb 128
#define Tt 512
#define Ee 256
#define Hh 128
#define FOURH 512

// ---------------------------------------------------------------------------
// Scratch (static device globals; no allocation anywhere)
// ---------------------------------------------------------------------------
__device__ float g_xw[(size_t)2 * Tt * Bb * FOURH];   // [dir][t][b][4H]  268MB
__device__ float g_h[2][2][Bb][Hh];                   // [phase][dir][b][h]
__device__ unsigned g_cnt[2];                         // per-direction barrier counters

// ---------------------------------------------------------------------------
// Reset kernel: zero h state (phase buffers) and barrier counters each replay
// ---------------------------------------------------------------------------
__global__ void reset_kernel() {
    int tid = blockIdx.x * blockDim.x + threadIdx.x;
    float* p = &g_h[0][0][0][0];
    const int n = 2 * 2 * Bb * Hh;
    for (int i = tid; i < n; i += gridDim.x * blockDim.x) p[i] = 0.0f;
    if (tid == 0) { g_cnt[0] = 0u; g_cnt[1] = 0u; }
}

// ---------------------------------------------------------------------------
// Projection GEMM: xw[dir][t][b][:] = emb[tokens[b][t]][:] @ W_dir
// M = T*B = 65536 (row = t*128 + b), K = 256, N = 512 per direction.
// BM=128, BN=128, BK=16, 256 threads, 8x8 microtile.
// ---------------------------------------------------------------------------
#define GBM 128
#define GBN 128
#define GBK 16

__global__ __launch_bounds__(256, 2)
void proj_kernel(const int* __restrict__ tokens,
                 const float* __restrict__ emb,
                 const float* __restrict__ Wfw,
                 const float* __restrict__ Wbw) {
    __shared__ float A_sm[GBK][GBM + 4];
    __shared__ float B_sm[GBK][GBN];
    __shared__ int   tok_sm[GBM];

    const int dir = blockIdx.z;
    const float* __restrict__ W = dir ? Wbw : Wfw;
    const int n0 = blockIdx.x * GBN;
    const int m0 = blockIdx.y * GBM;
    const int tid = threadIdx.x;

    if (tid < GBM) {
        int row = m0 + tid;
        int t = row >> 7;       // row / 128
        int b = row & 127;
        tok_sm[tid] = tokens[b * Tt + t];
    }
    __syncthreads();

    const int tr = tid >> 4;    // 0..15 -> rows tr*8..tr*8+7
    const int tc = tid & 15;    // 0..15 -> cols tc*8..tc*8+7

    float acc[8][8];
#pragma unroll
    for (int i = 0; i < 8; i++)
#pragma unroll
        for (int j = 0; j < 8; j++) acc[i][j] = 0.0f;

    for (int kt = 0; kt < Ee; kt += GBK) {
        // Load A tile (gathered embedding rows), store transposed [k][m]
#pragma unroll
        for (int q = tid; q < (GBM * GBK / 4); q += 256) {   // 512 float4s
            int row = q >> 2;           // 0..127
            int kq  = (q & 3) * 4;      // 0,4,8,12
            const float4 v = *(const float4*)(emb + (size_t)tok_sm[row] * Ee + kt + kq);
            A_sm[kq + 0][row] = v.x;
            A_sm[kq + 1][row] = v.y;
            A_sm[kq + 2][row] = v.z;
            A_sm[kq + 3][row] = v.w;
        }
        // Load B tile [k][n]
#pragma unroll
        for (int q = tid; q < (GBK * GBN / 4); q += 256) {   // 512 float4s
            int k  = q >> 5;            // 0..15
            int c4 = (q & 31) * 4;
            *(float4*)&B_sm[k][c4] = *(const float4*)(W + (size_t)(kt + k) * FOURH + n0 + c4);
        }
        __syncthreads();

#pragma unroll
        for (int k = 0; k < GBK; k++) {
            float a_reg[8], b_reg[8];
            *(float4*)&a_reg[0] = *(const float4*)&A_sm[k][tr * 8];
            *(float4*)&a_reg[4] = *(const float4*)&A_sm[k][tr * 8 + 4];
            *(float4*)&b_reg[0] = *(const float4*)&B_sm[k][tc * 8];
            *(float4*)&b_reg[4] = *(const float4*)&B_sm[k][tc * 8 + 4];
#pragma unroll
            for (int i = 0; i < 8; i++)
#pragma unroll
                for (int j = 0; j < 8; j++)
                    acc[i][j] = fmaf(a_reg[i], b_reg[j], acc[i][j]);
        }
        __syncthreads();
    }

    const size_t obase = (size_t)dir * ((size_t)Tt * Bb * FOURH);
#pragma unroll
    for (int i = 0; i < 8; i++) {
        size_t row = (size_t)(m0 + tr * 8 + i);
        float* dst = g_xw + obase + row * FOURH + n0 + tc * 8;
        *(float4*)(dst + 0) = *(float4*)&acc[i][0];
        *(float4*)(dst + 4) = *(float4*)&acc[i][4];
    }
}

// ---------------------------------------------------------------------------
// Persistent bidirectional LSTM recurrence.
// Grid = 128 CTAs: dir = bx>>6; within dir: 16 batch tiles (8 rows) x 4 unit
// tiles (32 units). 128 threads: thread = (bsub 0..3, jl 0..31), owns 2 batch
// rows and 1 hidden unit (all 4 gates). U column tile held in smem (float4,
// gate-interleaved) for the whole kernel. Per-direction grid barrier per step.
// ---------------------------------------------------------------------------
__device__ __forceinline__ float sigmoidf_(float x) {
    return 1.0f / (1.0f + __expf(-x));
}

#define LSTM_SMEM (128 * 32 * sizeof(float4) + 8 * 128 * sizeof(float))

__global__ __launch_bounds__(128, 1)
void lstm_kernel(const float* __restrict__ Ufw,
                 const float* __restrict__ Ubw,
                 const float* __restrict__ bfw,
                 const float* __restrict__ bbw,
                 float* __restrict__ out) {
    extern __shared__ char smem_raw[];
    float4 (*U4)[32]  = (float4(*)[32])smem_raw;                          // [k][jl] 64KB
    float  (*h_sm)[128] = (float(*)[128])(smem_raw + 128 * 32 * sizeof(float4)); // [bl][k] 4KB

    const int bx    = blockIdx.x;
    const int dir   = bx >> 6;
    const int id    = bx & 63;
    const int btile = id >> 2;      // 0..15
    const int utile = id & 3;       // 0..3
    const int tid   = threadIdx.x;
    const int jl    = tid & 31;
    const int bsub  = tid >> 5;     // 0..3

    const int j   = utile * 32 + jl;        // global hidden unit
    const int bl0 = bsub * 2;               // local batch rows
    const int bl1 = bl0 + 1;
    const int b0  = btile * 8 + bl0;
    const int b1  = b0 + 1;

    const float* __restrict__ U    = dir ? Ubw : Ufw;
    const float* __restrict__ bias = dir ? bbw : bfw;

    // Load U column tile: U[k][g*128 + j] -> U4[k][jl] (gate interleaved)
    for (int k = bsub; k < 128; k += 4) {
        const float* up = U + (size_t)k * FOURH + j;
        U4[k][jl] = make_float4(up[0], up[128], up[256], up[384]);
    }
    const float bz0 = bias[0 * Hh + j];
    const float bz1 = bias[1 * Hh + j];
    const float bz2 = bias[2 * Hh + j];
    const float bz3 = bias[3 * Hh + j];

    float c0 = 0.0f, c1 = 0.0f;
    float hout0 = 0.0f, hout1 = 0.0f;

    const size_t xw_dir = (size_t)dir * ((size_t)Tt * Bb * FOURH);

    for (int t = 0; t < Tt; t++) {
        const int tt = dir ? (Tt - 1 - t) : t;
        const int phase = t & 1;

        // Load h_prev tile into smem (L2-coherent reads)
        {
            const float* hp = &g_h[phase][dir][btile * 8][0];
#pragma unroll
            for (int i = tid; i < 8 * 128; i += 128) {
                ((float*)h_sm)[i] = __ldcg(hp + i);
            }
        }

        // Prefetch xw for this step (consumed after the dot loop)
        const float* xwp = g_xw + xw_dir + ((size_t)tt * Bb) * FOURH;
        const float x00 = __ldg(xwp + (size_t)b0 * FOURH + 0 * Hh + j);
        const float x01 = __ldg(xwp + (size_t)b0 * FOURH + 1 * Hh + j);
        const float x02 = __ldg(xwp + (size_t)b0 * FOURH + 2 * Hh + j);
        const float x03 = __ldg(xwp + (size_t)b0 * FOURH + 3 * Hh + j);
        const float x10 = __ldg(xwp + (size_t)b1 * FOURH + 0 * Hh + j);
        const float x11 = __ldg(xwp + (size_t)b1 * FOURH + 1 * Hh + j);
        const float x12 = __ldg(xwp + (size_t)b1 * FOURH + 2 * Hh + j);
        const float x13 = __ldg(xwp + (size_t)b1 * FOURH + 3 * Hh + j);

        __syncthreads();

        float a00 = bz0, a01 = bz1, a02 = bz2, a03 = bz3;
        float a10 = bz0, a11 = bz1, a12 = bz2, a13 = bz3;

#pragma unroll 8
        for (int k = 0; k < 128; k++) {
            const float4 u  = U4[k][jl];
            const float  h0 = h_sm[bl0][k];
            const float  h1 = h_sm[bl1][k];
            a00 = fmaf(h0, u.x, a00); a01 = fmaf(h0, u.y, a01);
            a02 = fmaf(h0, u.z, a02); a03 = fmaf(h0, u.w, a03);
            a10 = fmaf(h1, u.x, a10); a11 = fmaf(h1, u.y, a11);
            a12 = fmaf(h1, u.z, a12); a13 = fmaf(h1, u.w, a13);
        }

        a00 += x00; a01 += x01; a02 += x02; a03 += x03;
        a10 += x10; a11 += x11; a12 += x12; a13 += x13;

        // Gates (Keras order i, f, g, o)
        {
            const float ig = sigmoidf_(a00);
            const float fg = sigmoidf_(a01);
            const float gg = tanhf(a02);
            const float og = sigmoidf_(a03);
            c0 = fg * c0 + ig * gg;
            hout0 = og * tanhf(c0);
        }
        {
            const float ig = sigmoidf_(a10);
            const float fg = sigmoidf_(a11);
            const float gg = tanhf(a12);
            const float og = sigmoidf_(a13);
            c1 = fg * c1 + ig * gg;
            hout1 = og * tanhf(c1);
        }

        // Write hs into out[b][tt][dir*128 + j]
        out[((size_t)b0 * Tt + tt) * 256 + dir * Hh + j] = hout0;
        out[((size_t)b1 * Tt + tt) * 256 + dir * Hh + j] = hout1;
        // Publish h for next step (L2-coherent)
        __stcg(&g_h[phase ^ 1][dir][b0][j], hout0);
        __stcg(&g_h[phase ^ 1][dir][b1][j], hout1);

        if (t < Tt - 1) {
            // Per-direction grid barrier
            __threadfence();
            __syncthreads();
            if (tid == 0) {
                __threadfence();
                atomicAdd(&g_cnt[dir], 1u);
                const unsigned target = 64u * (unsigned)(t + 1);
                while (*((volatile unsigned*)&g_cnt[dir]) < target) { __nanosleep(40); }
                __threadfence();
            }
            __syncthreads();
        }
    }

    // Final states: out layout after [B,T,2H]: h_fw [B,H], c_fw, h_bw, c_bw
    const size_t fin = (size_t)Bb * Tt * 256 + (size_t)dir * 2 * Bb * Hh;
    out[fin + (size_t)b0 * Hh + j]            = hout0;
    out[fin + (size_t)b1 * Hh + j]            = hout1;
    out[fin + Bb * Hh + (size_t)b0 * Hh + j]  = c0;
    out[fin + Bb * Hh + (size_t)b1 * Hh + j]  = c1;
}

// ---------------------------------------------------------------------------
// Launch
// Inputs: tokens[int32 B*T], emb[V*E], W_fw[E*4H], U_fw[H*4H], b_fw[4H],
//         W_bw, U_bw, b_bw
// Output: float32, B*T*2H + 4*B*H
// ---------------------------------------------------------------------------
extern "C" void kernel_launch(void* const* d_in, const int* in_sizes, int n_in,
                              void* d_out, int out_size) {
    const int*   tokens = (const int*)d_in[0];
    const float* emb    = (const float*)d_in[1];
    const float* Wfw    = (const float*)d_in[2];
    const float* Ufw    = (const float*)d_in[3];
    const float* bfw    = (const float*)d_in[4];
    const float* Wbw    = (const float*)d_in[5];
    const float* Ubw    = (const float*)d_in[6];
    const float* bbw    = (const float*)d_in[7];
    float* out = (float*)d_out;

    static bool attr_set = false;
    if (!attr_set) {
        cudaFuncSetAttribute(lstm_kernel,
                             cudaFuncAttributeMaxDynamicSharedMemorySize,
                             (int)LSTM_SMEM);
        attr_set = true;
    }

    reset_kernel<<<64, 256>>>();
    proj_kernel<<<dim3(FOURH / GBN, (Tt * Bb) / GBM, 2), 256>>>(tokens, emb, Wfw, Wbw);
    lstm_kernel<<<128, 128, LSTM_SMEM>>>(Ufw, Ubw, bfw, bbw, out);
}